// round 9
// baseline (speedup 1.0000x reference)
#include <cuda_runtime.h>

#define NN    8192      // nodes
#define SDIM  64        // input dim
#define HH    4         // heads
#define ODIM  32        // out dim
#define EMAX  131072    // edges
#define ALPHA 0.2f

// ---------------- device scratch (no allocations allowed) ----------------
__device__ float  g_nv[EMAX];         // per-edge exp(score)
__device__ float4 g_ss[NN];           // per-node src scores, 4 heads
__device__ float4 g_sd[NN];           // per-node dst scores, 4 heads
__device__ float  g_csum[NN];         // per-column (dst) sum of exp

// 1) fused prep+scores: each block (8 nodes) recomputes w_eff into smem
//    (cheap: W,a come from L2), zeros its csum slice, then does the
//    8-head dot products, one warp per node.
__global__ void scores_kernel(const float* __restrict__ x,
                              const float* __restrict__ W,
                              const float* __restrict__ a) {
    __shared__ float sweff[8 * SDIM];     // [v*4+h][s]
    int tid = threadIdx.x;                // 256
    int blk = blockIdx.x;                 // 1024 blocks, 8 nodes each

    // w_eff[v][h][s] = sum_o W[h][s][o] * a[h][v*O + o]
    #pragma unroll
    for (int k = tid; k < 8 * SDIM; k += 256) {
        int v = k >> 8;          // 0..1
        int h = (k >> 6) & 3;    // 0..3
        int s = k & 63;          // 0..63
        const float* Wr = W + h * (SDIM * ODIM) + s * ODIM;
        const float* ar = a + h * (2 * ODIM) + v * ODIM;
        float acc = 0.0f;
        #pragma unroll
        for (int o = 0; o < ODIM; o++) acc += Wr[o] * ar[o];
        sweff[k] = acc;
    }
    if (tid < 8) g_csum[blk * 8 + tid] = 0.0f;
    __syncthreads();

    int warp = tid >> 5;
    int lane = tid & 31;
    int node = blk * 8 + warp;
    float x0 = x[node * SDIM + lane];
    float x1 = x[node * SDIM + 32 + lane];
    float acc[8];
    #pragma unroll
    for (int i = 0; i < 8; i++) {
        float w0 = sweff[i * SDIM + lane];
        float w1 = sweff[i * SDIM + 32 + lane];
        acc[i] = x0 * w0 + x1 * w1;
    }
    #pragma unroll
    for (int off = 16; off > 0; off >>= 1) {
        #pragma unroll
        for (int i = 0; i < 8; i++)
            acc[i] += __shfl_down_sync(0xffffffffu, acc[i], off);
    }
    if (lane == 0) {
        g_ss[node] = make_float4(acc[0], acc[1], acc[2], acc[3]);
        g_sd[node] = make_float4(acc[4], acc[5], acc[6], acc[7]);
    }
}

// 2) per-edge score, exp (scores bounded << 88: no max shift), column sum.
__global__ void edge_kernel(const int* __restrict__ edges,
                            const float* __restrict__ values,
                            const float* __restrict__ wlin,
                            const float* __restrict__ blin, int E) {
    int e = blockIdx.x * blockDim.x + threadIdx.x;
    if (e >= E) return;
    int src = edges[e];
    int dst = edges[E + e];
    float4 ss = g_ss[src];
    float4 sd = g_sd[dst];
    float t0 = ss.x + sd.x; t0 = t0 > 0.0f ? t0 : ALPHA * t0;
    float t1 = ss.y + sd.y; t1 = t1 > 0.0f ? t1 : ALPHA * t1;
    float t2 = ss.z + sd.z; t2 = t2 > 0.0f ? t2 : ALPHA * t2;
    float t3 = ss.w + sd.w; t3 = t3 > 0.0f ? t3 : ALPHA * t3;
    float mt = blin[0] + wlin[0] * t0 + wlin[1] * t1 + wlin[2] * t2 + wlin[3] * t3;
    float ex = expf(values[e] * mt);
    g_nv[e] = ex;
    atomicAdd(&g_csum[dst], ex);
}

// 3) scatter normalized softmax values to edge positions (after memset)
__global__ void scatter_kernel(const int* __restrict__ edges,
                               float* __restrict__ out, int E, int n) {
    int e = blockIdx.x * blockDim.x + threadIdx.x;
    if (e >= E) return;
    int src = edges[e];
    int dst = edges[E + e];
    out[(long)src * n + dst] = g_nv[e] / g_csum[dst];
}

extern "C" void kernel_launch(void* const* d_in, const int* in_sizes, int n_in,
                              void* d_out, int out_size) {
    const float* x      = (const float*)d_in[0];
    const int*   edges  = (const int*)d_in[1];
    const float* values = (const float*)d_in[2];
    const float* W      = (const float*)d_in[3];
    const float* a      = (const float*)d_in[4];
    const float* wlin   = (const float*)d_in[5];
    const float* blin   = (const float*)d_in[6];
    float* out = (float*)d_out;

    int E = in_sizes[1] / 2;          // edges is [2, E]
    (void)n_in;

    scores_kernel<<<NN / 8, 256>>>(x, W, a);
    edge_kernel<<<(E + 255) / 256, 256>>>(edges, values, wlin, blin, E);
    cudaMemsetAsync(out, 0, (size_t)out_size * sizeof(float), 0);
    scatter_kernel<<<(E + 255) / 256, 256>>>(edges, out, E, NN);
}

// round 10
// speedup vs baseline: 1.3614x; 1.3614x over previous
#include <cuda_runtime.h>

#define NN    8192      // nodes
#define SDIM  64        // input dim
#define ODIM  32        // out dim
#define EMAX  131072    // edges
#define ALPHA 0.2f

// ---------------- device scratch (no allocations allowed) ----------------
__device__ float    g_weff[8 * SDIM]; // [v*4+h][s]
__device__ float4   g_ss[NN];         // per-node src scores (4 heads)
__device__ float4   g_sd[NN];         // per-node dst scores (4 heads)
__device__ float    g_nv[EMAX];       // per-edge exp(score)
__device__ float    g_csum[NN];       // per-column (dst) sum of exp
__device__ unsigned g_bar_count;      // grid barrier arrivals (zero-init)
__device__ unsigned g_bar_gen;        // grid barrier generation

// sense-reversing software grid barrier (all blocks guaranteed resident)
__device__ __forceinline__ void gbar(unsigned nb) {
    __syncthreads();
    if (threadIdx.x == 0) {
        __threadfence();
        volatile unsigned* vgen = &g_bar_gen;
        unsigned gen = *vgen;
        if (atomicAdd(&g_bar_count, 1u) == nb - 1u) {
            g_bar_count = 0u;
            __threadfence();
            atomicAdd(&g_bar_gen, 1u);
        } else {
            while (*vgen == gen) { __nanosleep(64); }
        }
        __threadfence();
    }
    __syncthreads();
}

__global__ void __launch_bounds__(256)
gat_persistent(const float* __restrict__ x, const int* __restrict__ edges,
               const float* __restrict__ values, const float* __restrict__ W,
               const float* __restrict__ a, const float* __restrict__ wlin,
               const float* __restrict__ blin, float* __restrict__ out,
               int E, unsigned nblocks)
{
    __shared__ float sweff[8 * SDIM];
    const int tid  = threadIdx.x;
    const int warp = tid >> 5;
    const int lane = tid & 31;
    const unsigned gid      = blockIdx.x * 256u + tid;
    const unsigned nthreads = nblocks * 256u;

    // ---- Phase A: w_eff (blocks 0..63, warp-per-entry) + csum zero + fill ----
    if (blockIdx.x < 64) {
        int entry = blockIdx.x * 8 + warp;      // 0..511
        int v = entry >> 8;                     // 0..1
        int h = (entry >> 6) & 3;               // 0..3
        int s = entry & 63;                     // 0..63
        const float* Wr = W + h * (SDIM * ODIM) + s * ODIM;
        const float* ar = a + h * (2 * ODIM) + v * ODIM;
        float p = Wr[lane] * ar[lane];          // ODIM==32 == warp size
        #pragma unroll
        for (int off = 16; off > 0; off >>= 1)
            p += __shfl_down_sync(0xffffffffu, p, off);
        if (lane == 0) g_weff[entry] = p;
    }
    for (unsigned i = gid; i < NN; i += nthreads) g_csum[i] = 0.0f;
    {
        float4 z = make_float4(0.f, 0.f, 0.f, 0.f);
        float4* o4 = (float4*)out;
        const unsigned long n4 = (unsigned long)NN * NN / 4;
        #pragma unroll 4
        for (unsigned long i = gid; i < n4; i += nthreads) o4[i] = z;
    }
    gbar(nblocks);

    // ---- Phase B: scores, warp-per-node, w_eff staged in smem ----
    #pragma unroll
    for (int k = tid; k < 8 * SDIM; k += 256) sweff[k] = g_weff[k];
    __syncthreads();
    {
        const unsigned gwarp  = blockIdx.x * 8u + warp;
        const unsigned nwarps = nblocks * 8u;
        for (unsigned node = gwarp; node < NN; node += nwarps) {
            float x0 = x[node * SDIM + lane];
            float x1 = x[node * SDIM + 32 + lane];
            float acc[8];
            #pragma unroll
            for (int i = 0; i < 8; i++)
                acc[i] = x0 * sweff[i * SDIM + lane] + x1 * sweff[i * SDIM + 32 + lane];
            #pragma unroll
            for (int off = 16; off > 0; off >>= 1) {
                #pragma unroll
                for (int i = 0; i < 8; i++)
                    acc[i] += __shfl_down_sync(0xffffffffu, acc[i], off);
            }
            if (lane == 0) {
                g_ss[node] = make_float4(acc[0], acc[1], acc[2], acc[3]);
                g_sd[node] = make_float4(acc[4], acc[5], acc[6], acc[7]);
            }
        }
    }
    gbar(nblocks);

    // ---- Phase C: per-edge exp + column sum (scores << 88: no max shift) ----
    {
        float w0 = wlin[0], w1 = wlin[1], w2 = wlin[2], w3 = wlin[3], b0 = blin[0];
        for (unsigned e = gid; e < (unsigned)E && e < EMAX; e += nthreads) {
            int src = edges[e];
            int dst = edges[E + e];
            float4 ss = g_ss[src];
            float4 sd = g_sd[dst];
            float t0 = ss.x + sd.x; t0 = t0 > 0.f ? t0 : ALPHA * t0;
            float t1 = ss.y + sd.y; t1 = t1 > 0.f ? t1 : ALPHA * t1;
            float t2 = ss.z + sd.z; t2 = t2 > 0.f ? t2 : ALPHA * t2;
            float t3 = ss.w + sd.w; t3 = t3 > 0.f ? t3 : ALPHA * t3;
            float mt = b0 + w0 * t0 + w1 * t1 + w2 * t2 + w3 * t3;
            float ex = expf(values[e] * mt);
            g_nv[e] = ex;
            atomicAdd(&g_csum[dst], ex);
        }
    }
    gbar(nblocks);

    // ---- Phase D: scatter normalized values ----
    for (unsigned e = gid; e < (unsigned)E && e < EMAX; e += nthreads) {
        int src = edges[e];
        int dst = edges[E + e];
        out[(long)src * NN + dst] = g_nv[e] / g_csum[dst];
    }
}

extern "C" void kernel_launch(void* const* d_in, const int* in_sizes, int n_in,
                              void* d_out, int out_size) {
    const float* x      = (const float*)d_in[0];
    const int*   edges  = (const int*)d_in[1];
    const float* values = (const float*)d_in[2];
    const float* W      = (const float*)d_in[3];
    const float* a      = (const float*)d_in[4];
    const float* wlin   = (const float*)d_in[5];
    const float* blin   = (const float*)d_in[6];
    float* out = (float*)d_out;

    int E = in_sizes[1] / 2;          // edges is [2, E]
    (void)n_in; (void)out_size;

    // Grid = exactly the co-resident capacity (queried once, cached: the
    // correctness call happens before graph capture, so this is capture-safe
    // and deterministic across replays).
    static int g_nblocks = 0;
    if (g_nblocks == 0) {
        int dev = 0;
        cudaGetDevice(&dev);
        cudaDeviceProp prop;
        cudaGetDeviceProperties(&prop, dev);
        int bps = 0;
        cudaOccupancyMaxActiveBlocksPerMultiprocessor(&bps, gat_persistent, 256, 0);
        if (bps < 1) bps = 1;
        g_nblocks = bps * prop.multiProcessorCount;
        if (g_nblocks < 64) g_nblocks = 64;   // phase A needs 64 blocks
    }

    gat_persistent<<<g_nblocks, 256>>>(x, edges, values, W, a, wlin, blin,
                                       out, E, (unsigned)g_nblocks);
}